// round 16
// baseline (speedup 1.0000x reference)
#include <cuda_runtime.h>
#include <cuda_bf16.h>
#include <stdint.h>
#include <math.h>

// q pre-scale: 1/sqrt(32) * log2(e)  (so attn can use exp2f directly)
#define SCALE_Q_EXP2 (0.17677669529663687f * 1.4426950408889634f)

// Scratch (static __device__; no allocations allowed)
__device__ __nv_bfloat16 g_znhl[65536*64];     // [r][znh(32)|znl(32)]
__device__ __nv_bfloat16 g_qhl[1024*256*64];   // [ih][j][qh(32)|ql(32)] (pre-scaled)
__device__ __nv_bfloat16 g_khl[1024*256*64];   // [ih][j][kh|kl]
__device__ __nv_bfloat16 g_vhl[1024*256*64];   // [ih][j][vh|vl]
__device__ float g_gate[1024*256*32];
__device__ __nv_bfloat16 g_ohl[65536*256];     // [r][oh(128)|ol(128)], col = h*32+c
__device__ uint32_t g_wsp[4*4096];             // Wq/Wk/Wv/Wg split: [mat][row*32 + w]
__device__ uint32_t g_wo[4096];                // Wo split: [row*128 + (0..63 hi | 64..127 lo)]

// Fast pair convert: result low16 = bf16(a), high16 = bf16(b) (1 instr)
__device__ __forceinline__ uint32_t cvt2_bf16(float a, float b) {
    uint32_t r;
    asm("cvt.rn.bf16x2.f32 %0, %1, %2;" : "=r"(r) : "f"(b), "f"(a));
    return r;
}
// Fast split: returns hi pair, residuals via bit reconstruction
__device__ __forceinline__ uint32_t split2(float a, float b, float* la, float* lb) {
    uint32_t h = cvt2_bf16(a, b);
    *la = a - __uint_as_float(h << 16);
    *lb = b - __uint_as_float(h & 0xffff0000u);
    return h;
}

// m16n8k16 row.col bf16 -> f32 accumulate (sm_80+ PTX, valid on compute_103)
__device__ __forceinline__ void mma16816(float* d, const uint32_t* a,
                                         uint32_t b0, uint32_t b1) {
    asm volatile(
        "mma.sync.aligned.m16n8k16.row.col.f32.bf16.bf16.f32 "
        "{%0,%1,%2,%3}, {%4,%5,%6,%7}, {%8,%9}, {%0,%1,%2,%3};"
        : "+f"(d[0]), "+f"(d[1]), "+f"(d[2]), "+f"(d[3])
        : "r"(a[0]), "r"(a[1]), "r"(a[2]), "r"(a[3]), "r"(b0), "r"(b1));
}

// ---------------------------------------------------------------------------
// Kernel 0: one-time weight split (fp32 -> bf16 hi/lo words in global).
// 40 blocks x 256 threads = 10240 threads, one float-pair each.
// ---------------------------------------------------------------------------
__global__ __launch_bounds__(256) void wsplit_kernel(
    const float* __restrict__ Wq, const float* __restrict__ Wk,
    const float* __restrict__ Wv, const float* __restrict__ Wg,
    const float* __restrict__ Wo)
{
    const int gid = blockIdx.x * 256 + threadIdx.x;   // 0..10239
    const int mat = gid >> 11;                         // /2048
    const int p   = gid & 2047;
    if (mat < 4) {
        const float* W = (mat == 0) ? Wq : (mat == 1) ? Wk : (mat == 2) ? Wv : Wg;
        const int row = p >> 4, i = p & 15;            // 16 pairs per 32-float row
        float a = W[row*32 + 2*i], b = W[row*32 + 2*i + 1];
        float la, lb;
        uint32_t hi = split2(a, b, &la, &lb);
        g_wsp[mat*4096 + row*32 + i]      = hi;
        g_wsp[mat*4096 + row*32 + 16 + i] = cvt2_bf16(la, lb);
    } else {
        const int row = p >> 6, i = p & 63;            // 64 pairs per 128-float row
        float a = Wo[row*128 + 2*i], b = Wo[row*128 + 2*i + 1];
        float la, lb;
        uint32_t hi = split2(a, b, &la, &lb);
        g_wo[row*128 + i]      = hi;
        g_wo[row*128 + 64 + i] = cvt2_bf16(la, lb);
    }
}

// ---------------------------------------------------------------------------
// Kernel 1a: LayerNorm only -> zn bf16 hi/lo rows
// ---------------------------------------------------------------------------
__global__ __launch_bounds__(256) void ln_kernel(
    const float* __restrict__ z, const float* __restrict__ ln_g,
    const float* __restrict__ ln_b)
{
    __shared__ float sg[32], sb[32];
    const int tid = threadIdx.x;
    if (tid < 32) { sg[tid] = ln_g[tid]; sb[tid] = ln_b[tid]; }
    __syncthreads();

    const int r = blockIdx.x * 256 + tid;
    float x[32];
    const float4* zp = (const float4*)(z + (size_t)r * 32);
    #pragma unroll
    for (int c4 = 0; c4 < 8; ++c4) {
        float4 t = zp[c4];
        x[c4*4+0]=t.x; x[c4*4+1]=t.y; x[c4*4+2]=t.z; x[c4*4+3]=t.w;
    }
    float mu = 0.f;
    #pragma unroll
    for (int c = 0; c < 32; ++c) mu += x[c];
    mu *= (1.f/32.f);
    float var = 0.f;
    #pragma unroll
    for (int c = 0; c < 32; ++c) { float d = x[c]-mu; var += d*d; }
    var *= (1.f/32.f);
    const float inv = rsqrtf(var + 1e-5f);

    __nv_bfloat16* row = g_znhl + (size_t)r * 64;
    #pragma unroll
    for (int c = 0; c < 32; c += 2) {
        float a = (x[c]-mu)*inv*sg[c] + sb[c];
        float b = (x[c+1]-mu)*inv*sg[c+1] + sb[c+1];
        float la, lb;
        uint32_t hi = split2(a, b, &la, &lb);
        *(uint32_t*)(row + c)      = hi;
        *(uint32_t*)(row + 32 + c) = cvt2_bf16(la, lb);
    }
}

// ---------------------------------------------------------------------------
// Kernel 1b: projections as split-bf16 HMMA GEMM (weights pre-split).
// ---------------------------------------------------------------------------
__global__ __launch_bounds__(256) void projmm_kernel(const float* __restrict__ bg)
{
    __shared__ uint32_t sW[128*36];
    __shared__ uint32_t sA[64*36];
    __shared__ float sbg[128];

    const int tid = threadIdx.x;
    const int mat = blockIdx.x & 3;
    const int r0  = (blockIdx.x >> 2) * 64;

    // Stage pre-split weights (straight copy, pitch 32 -> 36)
    {
        const uint32_t* ws = g_wsp + mat*4096;
        for (int x = tid; x < 4096; x += 256) {
            int row = x >> 5, w = x & 31;
            sW[row*36 + w] = ws[x];
        }
    }
    if (tid < 128) sbg[tid] = bg[tid];
    {
        const uint2* ag = (const uint2*)(g_znhl + (size_t)r0 * 64);
        uint2* sA2 = (uint2*)sA;
        for (int x = tid; x < 1024; x += 256) {
            int row = x >> 4, w = x & 15;
            sA2[row*18 + w] = ag[row*16 + w];
        }
    }
    __syncthreads();

    const int warp = tid >> 5, lane = tid & 31;
    const int l4 = lane & 3, ld4 = lane >> 2;
    const int mrow = (warp & 1) * 32;
    const int ncol = (warp >> 1) * 32;

    uint32_t Ah[2][2][4], Al[2][2][4];
    #pragma unroll
    for (int mt = 0; mt < 2; ++mt)
    #pragma unroll
    for (int kt = 0; kt < 2; ++kt) {
        const int r = mrow + mt*16 + ld4;
        const uint32_t* p0 = sA + r*36 + kt*8 + l4;
        const uint32_t* p1 = sA + (r+8)*36 + kt*8 + l4;
        Ah[mt][kt][0] = p0[0];  Ah[mt][kt][1] = p1[0];
        Ah[mt][kt][2] = p0[4];  Ah[mt][kt][3] = p1[4];
        Al[mt][kt][0] = p0[16]; Al[mt][kt][1] = p1[16];
        Al[mt][kt][2] = p0[20]; Al[mt][kt][3] = p1[20];
    }

    const int ig = r0 >> 8;
    #pragma unroll
    for (int nt = 0; nt < 4; ++nt) {
        const int n = ncol + nt*8 + ld4;
        const uint32_t* wp = sW + n*36 + l4;
        uint32_t bh[2][2], bl[2][2];
        bh[0][0]=wp[0];  bh[0][1]=wp[4];  bh[1][0]=wp[8];  bh[1][1]=wp[12];
        bl[0][0]=wp[16]; bl[0][1]=wp[20]; bl[1][0]=wp[24]; bl[1][1]=wp[28];
        #pragma unroll
        for (int mt = 0; mt < 2; ++mt) {
            float s[4] = {0,0,0,0}, s2[4] = {0,0,0,0};
            mma16816(s,  Ah[mt][0], bh[0][0], bh[0][1]);
            mma16816(s,  Ah[mt][1], bh[1][0], bh[1][1]);
            mma16816(s2, Ah[mt][0], bl[0][0], bl[0][1]);
            mma16816(s2, Ah[mt][1], bl[1][0], bl[1][1]);
            mma16816(s2, Al[mt][0], bh[0][0], bh[0][1]);
            mma16816(s2, Al[mt][1], bh[1][0], bh[1][1]);
            #pragma unroll
            for (int u = 0; u < 4; ++u) s[u] += s2[u];

            const int rg0 = r0 + mrow + mt*16 + ld4;
            const int ocol = ncol + nt*8 + l4*2;
            const int h = ocol >> 5, c = ocol & 31;
            const int j0 = rg0 & 255;
            const size_t base = ((size_t)(ig*4 + h)*256);
            if (mat == 3) {
                float* g0 = g_gate + (base + j0)*32;
                float* g1 = g_gate + (base + j0 + 8)*32;
                *(float2*)(g0 + c) = make_float2(
                    1.f/(1.f+__expf(-(s[0]+sbg[ocol]))), 1.f/(1.f+__expf(-(s[1]+sbg[ocol+1]))));
                *(float2*)(g1 + c) = make_float2(
                    1.f/(1.f+__expf(-(s[2]+sbg[ocol]))), 1.f/(1.f+__expf(-(s[3]+sbg[ocol+1]))));
            } else {
                if (mat == 0) {
                    #pragma unroll
                    for (int u = 0; u < 4; ++u) s[u] *= SCALE_Q_EXP2;
                }
                __nv_bfloat16* dst = (mat == 0) ? g_qhl : (mat == 1) ? g_khl : g_vhl;
                __nv_bfloat16* d0 = dst + (base + j0)*64;
                __nv_bfloat16* d1 = dst + (base + j0 + 8)*64;
                float la, lb;
                uint32_t hi0 = split2(s[0], s[1], &la, &lb);
                *(uint32_t*)(d0 + c)      = hi0;
                *(uint32_t*)(d0 + 32 + c) = cvt2_bf16(la, lb);
                uint32_t hi1 = split2(s[2], s[3], &la, &lb);
                *(uint32_t*)(d1 + c)      = hi1;
                *(uint32_t*)(d1 + 32 + c) = cvt2_bf16(la, lb);
            }
        }
    }
}

// ---------------------------------------------------------------------------
// Kernel 2: HMMA attention (unchanged from R14).
// ---------------------------------------------------------------------------
__global__ __launch_bounds__(256, 3) void attn_kernel()
{
    extern __shared__ __align__(16) char smem[];
    uint32_t* sK = (uint32_t*)smem;                       // 36864 B
    __nv_bfloat16* sVh = (__nv_bfloat16*)(sK + 256*36);   // 16896 B
    __nv_bfloat16* sVl = sVh + 32*264;                    // 16896 B

    const int tid = threadIdx.x;
    const int ih = blockIdx.x;
    const int warp = tid >> 5, lane = tid & 31;
    const int l4 = lane & 3, ld4 = lane >> 2;
    const int m0 = warp * 32;

    {
        const uint2* kg = (const uint2*)(g_khl + (size_t)ih*16384);
        uint2* sK2 = (uint2*)sK;
        for (int x = tid; x < 4096; x += 256) {
            int row = x >> 4, w = x & 15;
            sK2[row*18 + w] = kg[x];
        }
    }
    {
        const uint4* vg = (const uint4*)(g_vhl + (size_t)ih*16384) + tid*8;
        uint32_t vb[32];
        #pragma unroll
        for (int t = 0; t < 8; ++t) {
            uint4 u = vg[t];
            vb[t*4+0]=u.x; vb[t*4+1]=u.y; vb[t*4+2]=u.z; vb[t*4+3]=u.w;
        }
        const __nv_bfloat16* vbh = (const __nv_bfloat16*)vb;
        #pragma unroll
        for (int c = 0; c < 32; ++c) {
            sVh[c*264 + tid] = vbh[c];
            sVl[c*264 + tid] = vbh[32 + c];
        }
    }
    __syncthreads();

    const uint32_t* sVhw = (const uint32_t*)sVh;
    const uint32_t* sVlw = (const uint32_t*)sVl;
    const uint32_t* qgw = (const uint32_t*)(g_qhl + (size_t)ih*16384);
    const int rbase = (ih >> 2) * 256;
    const int cbase = (ih & 3) * 32;
    const size_t gbase = (size_t)ih * 8192;
    uint32_t* ow = (uint32_t*)g_ohl;

    #pragma unroll 1
    for (int mt = 0; mt < 2; ++mt) {
        uint32_t Qh[2][4], Ql[2][4];
        #pragma unroll
        for (int kt = 0; kt < 2; ++kt) {
            const int r = m0 + mt*16 + ld4;
            const uint32_t* p0 = qgw + r*32 + kt*8 + l4;
            const uint32_t* p1 = qgw + (r+8)*32 + kt*8 + l4;
            Qh[kt][0] = p0[0];  Qh[kt][1] = p1[0];
            Qh[kt][2] = p0[4];  Qh[kt][3] = p1[4];
            Ql[kt][0] = p0[16]; Ql[kt][1] = p1[16];
            Ql[kt][2] = p0[20]; Ql[kt][3] = p1[20];
        }

        float acc[4][4];
        #pragma unroll
        for (int nt = 0; nt < 4; ++nt)
        #pragma unroll
        for (int u = 0; u < 4; ++u) acc[nt][u] = 0.f;
        float dsum0 = 0.f, dsum1 = 0.f;

        for (int ch = 0; ch < 8; ++ch) {
            #pragma unroll
            for (int kt = 0; kt < 2; ++kt) {
                uint32_t Ph[4], Pl[4];
                #pragma unroll
                for (int nt2 = 0; nt2 < 2; ++nt2) {
                    const int nt = kt*2 + nt2;
                    const int n = ch*32 + nt*8 + ld4;
                    const uint32_t* kp = sK + n*36 + l4;
                    uint32_t bh[2][2], bl[2][2];
                    bh[0][0]=kp[0];  bh[0][1]=kp[4];  bh[1][0]=kp[8];  bh[1][1]=kp[12];
                    bl[0][0]=kp[16]; bl[0][1]=kp[20]; bl[1][0]=kp[24]; bl[1][1]=kp[28];
                    float s[4] = {0,0,0,0}, s2[4] = {0,0,0,0};
                    mma16816(s,  Qh[0], bh[0][0], bh[0][1]);
                    mma16816(s,  Qh[1], bh[1][0], bh[1][1]);
                    mma16816(s2, Qh[0], bl[0][0], bl[0][1]);
                    mma16816(s2, Qh[1], bl[1][0], bl[1][1]);
                    mma16816(s2, Ql[0], bh[0][0], bh[0][1]);
                    mma16816(s2, Ql[1], bh[1][0], bh[1][1]);
                    const float e0 = exp2f(s[0]+s2[0]), e1 = exp2f(s[1]+s2[1]);
                    const float e2 = exp2f(s[2]+s2[2]), e3 = exp2f(s[3]+s2[3]);
                    dsum0 += e0 + e1;
                    dsum1 += e2 + e3;
                    float l0, l1, l2, l3;
                    Ph[nt2*2+0] = split2(e0, e1, &l0, &l1);
                    Ph[nt2*2+1] = split2(e2, e3, &l2, &l3);
                    Pl[nt2*2+0] = cvt2_bf16(l0, l1);
                    Pl[nt2*2+1] = cvt2_bf16(l2, l3);
                }
                #pragma unroll
                for (int ntc = 0; ntc < 4; ++ntc) {
                    const int c = ntc*8 + ld4;
                    const uint32_t* vhp = sVhw + c*132 + ch*16 + kt*8 + l4;
                    const uint32_t* vlp = sVlw + c*132 + ch*16 + kt*8 + l4;
                    const uint32_t vh0 = vhp[0], vh1 = vhp[4];
                    const uint32_t vl0 = vlp[0], vl1 = vlp[4];
                    mma16816(acc[ntc], Ph, vh0, vh1);
                    mma16816(acc[ntc], Ph, vl0, vl1);
                    mma16816(acc[ntc], Pl, vh0, vh1);
                }
            }
        }

        dsum0 += __shfl_xor_sync(0xffffffffu, dsum0, 1);
        dsum0 += __shfl_xor_sync(0xffffffffu, dsum0, 2);
        dsum1 += __shfl_xor_sync(0xffffffffu, dsum1, 1);
        dsum1 += __shfl_xor_sync(0xffffffffu, dsum1, 2);
        dsum0 = 1.f / dsum0;
        dsum1 = 1.f / dsum1;

        const int q0 = m0 + mt*16 + ld4;
        #pragma unroll
        for (int ntc = 0; ntc < 4; ++ntc) {
            const int c0 = ntc*8 + l4*2;
            const int wcol = (cbase + c0) >> 1;
            {
                float2 gv = *(const float2*)(g_gate + gbase + q0*32 + c0);
                float o0 = acc[ntc][0] * dsum0 * gv.x;
                float o1 = acc[ntc][1] * dsum0 * gv.y;
                float l0, l1;
                uint32_t hi = split2(o0, o1, &l0, &l1);
                uint32_t* base = ow + (size_t)(rbase + q0) * 128 + wcol;
                base[0]  = hi;
                base[64] = cvt2_bf16(l0, l1);
            }
            {
                float2 gv = *(const float2*)(g_gate + gbase + (q0+8)*32 + c0);
                float o0 = acc[ntc][2] * dsum1 * gv.x;
                float o1 = acc[ntc][3] * dsum1 * gv.y;
                float l0, l1;
                uint32_t hi = split2(o0, o1, &l0, &l1);
                uint32_t* base = ow + (size_t)(rbase + q0 + 8) * 128 + wcol;
                base[0]  = hi;
                base[64] = cvt2_bf16(l0, l1);
            }
        }
    }
}

// ---------------------------------------------------------------------------
// Kernel 3: out = o @ Wo.T + bo. 512 CTAs x 128 rows (occupancy fix);
// each warp one 16-row mt-tile; Wo pre-split (straight smem copy).
// ---------------------------------------------------------------------------
__global__ __launch_bounds__(256) void outmm_kernel(
    const float* __restrict__ bo, float* __restrict__ out)
{
    __shared__ uint32_t sW[32*132];
    __shared__ float sbo[32];
    const int tid = threadIdx.x;
    for (int x = tid; x < 4096; x += 256) {
        int row = x >> 7, w = x & 127;
        sW[row*132 + w] = g_wo[x];
    }
    if (tid < 32) sbo[tid] = bo[tid];
    __syncthreads();

    const int warp = tid >> 5, lane = tid & 31;
    const int l4 = lane & 3, ld4 = lane >> 2;
    const int m0 = blockIdx.x * 128 + warp * 16;

    float acc[4][4];
    #pragma unroll
    for (int nt = 0; nt < 4; ++nt)
    #pragma unroll
    for (int u = 0; u < 4; ++u) acc[nt][u] = 0.f;

    const uint32_t* A = (const uint32_t*)g_ohl;

    #pragma unroll
    for (int kc = 0; kc < 4; ++kc) {
        uint32_t Ah[2][4], Al[2][4];
        #pragma unroll
        for (int kt = 0; kt < 2; ++kt) {
            const uint32_t* p0 = A + (size_t)(m0 + ld4) * 128 + kc*16 + kt*8 + l4;
            const uint32_t* p1 = p0 + 8*128;
            Ah[kt][0] = p0[0];  Ah[kt][1] = p1[0];
            Ah[kt][2] = p0[4];  Ah[kt][3] = p1[4];
            Al[kt][0] = p0[64]; Al[kt][1] = p1[64];
            Al[kt][2] = p0[68]; Al[kt][3] = p1[68];
        }
        #pragma unroll
        for (int nt = 0; nt < 4; ++nt) {
            const uint32_t* wp = sW + (nt*8 + ld4)*132 + kc*16 + l4;
            uint32_t bh[2][2], bl[2][2];
            bh[0][0]=wp[0];  bh[0][1]=wp[4];  bh[1][0]=wp[8];  bh[1][1]=wp[12];
            bl[0][0]=wp[64]; bl[0][1]=wp[68]; bl[1][0]=wp[72]; bl[1][1]=wp[76];
            #pragma unroll
            for (int kt = 0; kt < 2; ++kt) {
                mma16816(acc[nt], Ah[kt], bh[kt][0], bh[kt][1]);
                mma16816(acc[nt], Ah[kt], bl[kt][0], bl[kt][1]);
                mma16816(acc[nt], Al[kt], bh[kt][0], bh[kt][1]);
            }
        }
    }

    const int r0 = m0 + ld4;
    #pragma unroll
    for (int nt = 0; nt < 4; ++nt) {
        const int c0 = nt*8 + l4*2;
        *(float2*)(out + (size_t)r0*32 + c0) =
            make_float2(acc[nt][0] + sbo[c0], acc[nt][1] + sbo[c0+1]);
        *(float2*)(out + (size_t)(r0+8)*32 + c0) =
            make_float2(acc[nt][2] + sbo[c0], acc[nt][3] + sbo[c0+1]);
    }
}

// ---------------------------------------------------------------------------
extern "C" void kernel_launch(void* const* d_in, const int* in_sizes, int n_in,
                              void* d_out, int out_size) {
    const float* z    = (const float*)d_in[0];
    const float* ln_g = (const float*)d_in[1];
    const float* ln_b = (const float*)d_in[2];
    const float* Wq   = (const float*)d_in[3];
    const float* Wk   = (const float*)d_in[4];
    const float* Wv   = (const float*)d_in[5];
    // d_in[6] = Wb: bias is constant along the softmax axis -> cancels exactly
    const float* Wg   = (const float*)d_in[7];
    const float* bg   = (const float*)d_in[8];
    const float* Wo   = (const float*)d_in[9];
    const float* bo   = (const float*)d_in[10];
    float* out = (float*)d_out;

    cudaFuncSetAttribute(attn_kernel, cudaFuncAttributeMaxDynamicSharedMemorySize, 70656);

    wsplit_kernel<<<40, 256>>>(Wq, Wk, Wv, Wg, Wo);
    ln_kernel<<<256, 256>>>(z, ln_g, ln_b);
    projmm_kernel<<<4096, 256>>>(bg);
    attn_kernel<<<1024, 256, 70656>>>();
    outmm_kernel<<<512, 256>>>(bo, out);
}

// round 17
// speedup vs baseline: 1.1160x; 1.1160x over previous
#include <cuda_runtime.h>
#include <cuda_bf16.h>
#include <stdint.h>
#include <math.h>

// q pre-scale: 1/sqrt(32) * log2(e)  (so attn can use exp2f directly)
#define SCALE_Q_EXP2 (0.17677669529663687f * 1.4426950408889634f)

// Scratch (static __device__; no allocations allowed)
__device__ __nv_bfloat16 g_znhl[65536*64];     // [r][znh(32)|znl(32)]
__device__ __nv_bfloat16 g_qhl[1024*256*64];   // [ih][j][qh(32)|ql(32)] (pre-scaled)
__device__ __nv_bfloat16 g_khl[1024*256*64];   // [ih][j][kh|kl]
__device__ __nv_bfloat16 g_vhl[1024*256*64];   // [ih][j][vh|vl]
__device__ float g_gate[1024*256*32];
__device__ __nv_bfloat16 g_ohl[65536*256];     // [r][oh(128)|ol(128)], col = h*32+c

// Fast pair convert: result low16 = bf16(a), high16 = bf16(b) (1 instr)
__device__ __forceinline__ uint32_t cvt2_bf16(float a, float b) {
    uint32_t r;
    asm("cvt.rn.bf16x2.f32 %0, %1, %2;" : "=r"(r) : "f"(b), "f"(a));
    return r;
}
// Fast split: returns hi pair, residuals via bit reconstruction
__device__ __forceinline__ uint32_t split2(float a, float b, float* la, float* lb) {
    uint32_t h = cvt2_bf16(a, b);
    *la = a - __uint_as_float(h << 16);
    *lb = b - __uint_as_float(h & 0xffff0000u);
    return h;
}

// m16n8k16 row.col bf16 -> f32 accumulate (sm_80+ PTX, valid on compute_103)
__device__ __forceinline__ void mma16816(float* d, const uint32_t* a,
                                         uint32_t b0, uint32_t b1) {
    asm volatile(
        "mma.sync.aligned.m16n8k16.row.col.f32.bf16.bf16.f32 "
        "{%0,%1,%2,%3}, {%4,%5,%6,%7}, {%8,%9}, {%0,%1,%2,%3};"
        : "+f"(d[0]), "+f"(d[1]), "+f"(d[2]), "+f"(d[3])
        : "r"(a[0]), "r"(a[1]), "r"(a[2]), "r"(a[3]), "r"(b0), "r"(b1));
}
// ldmatrix x4: lanes 0-7 address matrix0 rows, 8-15 m1, 16-23 m2, 24-31 m3.
__device__ __forceinline__ void ldm_x4(uint32_t& r0, uint32_t& r1,
                                       uint32_t& r2, uint32_t& r3, uint32_t addr) {
    asm volatile("ldmatrix.sync.aligned.m8n8.x4.shared.b16 {%0,%1,%2,%3}, [%4];"
                 : "=r"(r0), "=r"(r1), "=r"(r2), "=r"(r3) : "r"(addr));
}

// ---------------------------------------------------------------------------
// Kernel 1a: LayerNorm only -> zn bf16 hi/lo rows
// ---------------------------------------------------------------------------
__global__ __launch_bounds__(256) void ln_kernel(
    const float* __restrict__ z, const float* __restrict__ ln_g,
    const float* __restrict__ ln_b)
{
    __shared__ float sg[32], sb[32];
    const int tid = threadIdx.x;
    if (tid < 32) { sg[tid] = ln_g[tid]; sb[tid] = ln_b[tid]; }
    __syncthreads();

    const int r = blockIdx.x * 256 + tid;
    float x[32];
    const float4* zp = (const float4*)(z + (size_t)r * 32);
    #pragma unroll
    for (int c4 = 0; c4 < 8; ++c4) {
        float4 t = zp[c4];
        x[c4*4+0]=t.x; x[c4*4+1]=t.y; x[c4*4+2]=t.z; x[c4*4+3]=t.w;
    }
    float mu = 0.f;
    #pragma unroll
    for (int c = 0; c < 32; ++c) mu += x[c];
    mu *= (1.f/32.f);
    float var = 0.f;
    #pragma unroll
    for (int c = 0; c < 32; ++c) { float d = x[c]-mu; var += d*d; }
    var *= (1.f/32.f);
    const float inv = rsqrtf(var + 1e-5f);

    __nv_bfloat16* row = g_znhl + (size_t)r * 64;
    #pragma unroll
    for (int c = 0; c < 32; c += 2) {
        float a = (x[c]-mu)*inv*sg[c] + sb[c];
        float b = (x[c+1]-mu)*inv*sg[c+1] + sb[c+1];
        float la, lb;
        uint32_t hi = split2(a, b, &la, &lb);
        *(uint32_t*)(row + c)      = hi;
        *(uint32_t*)(row + 32 + c) = cvt2_bf16(la, lb);
    }
}

// ---------------------------------------------------------------------------
// Kernel 1b: projections as split-bf16 HMMA GEMM (R14 form: in-CTA split).
// ---------------------------------------------------------------------------
__global__ __launch_bounds__(256) void projmm_kernel(
    const float* __restrict__ Wq, const float* __restrict__ Wk,
    const float* __restrict__ Wv, const float* __restrict__ Wg,
    const float* __restrict__ bg)
{
    __shared__ uint32_t sW[128*36];
    __shared__ uint32_t sA[64*36];
    __shared__ float sbg[128];

    const int tid = threadIdx.x;
    const int mat = blockIdx.x & 3;
    const int r0  = (blockIdx.x >> 2) * 64;
    const float* W = (mat == 0) ? Wq : (mat == 1) ? Wk : (mat == 2) ? Wv : Wg;

    {
        const int row = tid >> 1, half = tid & 1;
        const float4* wp = (const float4*)(W + row*32 + half*16);
        #pragma unroll
        for (int q4 = 0; q4 < 4; ++q4) {
            float4 wv = wp[q4];
            float lx, ly, lz, lw;
            uint32_t h0 = split2(wv.x, wv.y, &lx, &ly);
            uint32_t h1 = split2(wv.z, wv.w, &lz, &lw);
            const int w0 = half*8 + q4*2;
            sW[row*36 + w0]      = h0;
            sW[row*36 + w0 + 1]  = h1;
            sW[row*36 + 16 + w0]     = cvt2_bf16(lx, ly);
            sW[row*36 + 16 + w0 + 1] = cvt2_bf16(lz, lw);
        }
    }
    if (tid < 128) sbg[tid] = bg[tid];
    {
        const uint2* ag = (const uint2*)(g_znhl + (size_t)r0 * 64);
        uint2* sA2 = (uint2*)sA;
        for (int x = tid; x < 1024; x += 256) {
            int row = x >> 4, w = x & 15;
            sA2[row*18 + w] = ag[row*16 + w];
        }
    }
    __syncthreads();

    const int warp = tid >> 5, lane = tid & 31;
    const int l4 = lane & 3, ld4 = lane >> 2;
    const int mrow = (warp & 1) * 32;
    const int ncol = (warp >> 1) * 32;

    uint32_t Ah[2][2][4], Al[2][2][4];
    #pragma unroll
    for (int mt = 0; mt < 2; ++mt)
    #pragma unroll
    for (int kt = 0; kt < 2; ++kt) {
        const int r = mrow + mt*16 + ld4;
        const uint32_t* p0 = sA + r*36 + kt*8 + l4;
        const uint32_t* p1 = sA + (r+8)*36 + kt*8 + l4;
        Ah[mt][kt][0] = p0[0];  Ah[mt][kt][1] = p1[0];
        Ah[mt][kt][2] = p0[4];  Ah[mt][kt][3] = p1[4];
        Al[mt][kt][0] = p0[16]; Al[mt][kt][1] = p1[16];
        Al[mt][kt][2] = p0[20]; Al[mt][kt][3] = p1[20];
    }

    const int ig = r0 >> 8;
    #pragma unroll
    for (int nt = 0; nt < 4; ++nt) {
        const int n = ncol + nt*8 + ld4;
        const uint32_t* wp = sW + n*36 + l4;
        uint32_t bh[2][2], bl[2][2];
        bh[0][0]=wp[0];  bh[0][1]=wp[4];  bh[1][0]=wp[8];  bh[1][1]=wp[12];
        bl[0][0]=wp[16]; bl[0][1]=wp[20]; bl[1][0]=wp[24]; bl[1][1]=wp[28];
        #pragma unroll
        for (int mt = 0; mt < 2; ++mt) {
            float s[4] = {0,0,0,0}, s2[4] = {0,0,0,0};
            mma16816(s,  Ah[mt][0], bh[0][0], bh[0][1]);
            mma16816(s,  Ah[mt][1], bh[1][0], bh[1][1]);
            mma16816(s2, Ah[mt][0], bl[0][0], bl[0][1]);
            mma16816(s2, Ah[mt][1], bl[1][0], bl[1][1]);
            mma16816(s2, Al[mt][0], bh[0][0], bh[0][1]);
            mma16816(s2, Al[mt][1], bh[1][0], bh[1][1]);
            #pragma unroll
            for (int u = 0; u < 4; ++u) s[u] += s2[u];

            const int rg0 = r0 + mrow + mt*16 + ld4;
            const int ocol = ncol + nt*8 + l4*2;
            const int h = ocol >> 5, c = ocol & 31;
            const int j0 = rg0 & 255;
            const size_t base = ((size_t)(ig*4 + h)*256);
            if (mat == 3) {
                float* g0 = g_gate + (base + j0)*32;
                float* g1 = g_gate + (base + j0 + 8)*32;
                *(float2*)(g0 + c) = make_float2(
                    1.f/(1.f+__expf(-(s[0]+sbg[ocol]))), 1.f/(1.f+__expf(-(s[1]+sbg[ocol+1]))));
                *(float2*)(g1 + c) = make_float2(
                    1.f/(1.f+__expf(-(s[2]+sbg[ocol]))), 1.f/(1.f+__expf(-(s[3]+sbg[ocol+1]))));
            } else {
                if (mat == 0) {
                    #pragma unroll
                    for (int u = 0; u < 4; ++u) s[u] *= SCALE_Q_EXP2;
                }
                __nv_bfloat16* dst = (mat == 0) ? g_qhl : (mat == 1) ? g_khl : g_vhl;
                __nv_bfloat16* d0 = dst + (base + j0)*64;
                __nv_bfloat16* d1 = dst + (base + j0 + 8)*64;
                float la, lb;
                uint32_t hi0 = split2(s[0], s[1], &la, &lb);
                *(uint32_t*)(d0 + c)      = hi0;
                *(uint32_t*)(d0 + 32 + c) = cvt2_bf16(la, lb);
                uint32_t hi1 = split2(s[2], s[3], &la, &lb);
                *(uint32_t*)(d1 + c)      = hi1;
                *(uint32_t*)(d1 + 32 + c) = cvt2_bf16(la, lb);
            }
        }
    }
}

// ---------------------------------------------------------------------------
// Kernel 2: HMMA attention. K/V fragments via ldmatrix.x4 (8 LDS -> 2 ldm
// for K per nt2; 4 LDS -> 1 ldm for V per ntc). Otherwise R14 structure.
// ---------------------------------------------------------------------------
__global__ __launch_bounds__(256, 3) void attn_kernel()
{
    extern __shared__ __align__(16) char smem[];
    uint32_t* sK = (uint32_t*)smem;                       // 36864 B, pitch 36 words
    __nv_bfloat16* sVh = (__nv_bfloat16*)(sK + 256*36);   // 16896 B, pitch 132 words
    __nv_bfloat16* sVl = sVh + 32*264;                    // 16896 B

    const int tid = threadIdx.x;
    const int ih = blockIdx.x;
    const int warp = tid >> 5, lane = tid & 31;
    const int l4 = lane & 3, ld4 = lane >> 2;
    const int m0 = warp * 32;

    {
        const uint2* kg = (const uint2*)(g_khl + (size_t)ih*16384);
        uint2* sK2 = (uint2*)sK;
        for (int x = tid; x < 4096; x += 256) {
            int row = x >> 4, w = x & 15;
            sK2[row*18 + w] = kg[x];
        }
    }
    {
        const uint4* vg = (const uint4*)(g_vhl + (size_t)ih*16384) + tid*8;
        uint32_t vb[32];
        #pragma unroll
        for (int t = 0; t < 8; ++t) {
            uint4 u = vg[t];
            vb[t*4+0]=u.x; vb[t*4+1]=u.y; vb[t*4+2]=u.z; vb[t*4+3]=u.w;
        }
        const __nv_bfloat16* vbh = (const __nv_bfloat16*)vb;
        #pragma unroll
        for (int c = 0; c < 32; ++c) {
            sVh[c*264 + tid] = vbh[c];
            sVl[c*264 + tid] = vbh[32 + c];
        }
    }
    __syncthreads();

    // Per-lane ldmatrix base addresses (shared address space)
    const uint32_t sKb = (uint32_t)__cvta_generic_to_shared(smem);
    const uint32_t sVb = sKb + 36864u;
    // K: matrix m = lane>>3 at word offset m*4; row = lane&7, pitch 36 words
    const uint32_t laneK = ((lane & 7)*36u + (lane >> 3)*4u) * 4u;
    // V: matrices 0,1 in sVh (word offs 0,4), matrices 2,3 in sVl (+16896 B)
    const uint32_t laneV = ((lane & 7)*132u + ((lane >> 3) & 1)*4u) * 4u
                         + ((uint32_t)(lane >> 4)) * 16896u;

    const uint32_t* qgw = (const uint32_t*)(g_qhl + (size_t)ih*16384);
    const int rbase = (ih >> 2) * 256;
    const int cbase = (ih & 3) * 32;
    const size_t gbase = (size_t)ih * 8192;
    uint32_t* ow = (uint32_t*)g_ohl;

    #pragma unroll 1
    for (int mt = 0; mt < 2; ++mt) {
        uint32_t Qh[2][4], Ql[2][4];
        #pragma unroll
        for (int kt = 0; kt < 2; ++kt) {
            const int r = m0 + mt*16 + ld4;
            const uint32_t* p0 = qgw + r*32 + kt*8 + l4;
            const uint32_t* p1 = qgw + (r+8)*32 + kt*8 + l4;
            Qh[kt][0] = p0[0];  Qh[kt][1] = p1[0];
            Qh[kt][2] = p0[4];  Qh[kt][3] = p1[4];
            Ql[kt][0] = p0[16]; Ql[kt][1] = p1[16];
            Ql[kt][2] = p0[20]; Ql[kt][3] = p1[20];
        }

        float acc[4][4];
        #pragma unroll
        for (int nt = 0; nt < 4; ++nt)
        #pragma unroll
        for (int u = 0; u < 4; ++u) acc[nt][u] = 0.f;
        float dsum0 = 0.f, dsum1 = 0.f;

        for (int ch = 0; ch < 8; ++ch) {
            #pragma unroll
            for (int kt = 0; kt < 2; ++kt) {
                uint32_t Ph[4], Pl[4];
                #pragma unroll
                for (int nt2 = 0; nt2 < 2; ++nt2) {
                    const int n0 = ch*32 + (kt*2 + nt2)*8;
                    const uint32_t aK = sKb + laneK + (uint32_t)n0 * 144u;
                    uint32_t bh0, bh1, bh2, bh3, bl0, bl1, bl2, bl3;
                    ldm_x4(bh0, bh1, bh2, bh3, aK);        // hi: k 0-31
                    ldm_x4(bl0, bl1, bl2, bl3, aK + 64u);  // lo: k 0-31
                    float s[4] = {0,0,0,0}, s2[4] = {0,0,0,0};
                    mma16816(s,  Qh[0], bh0, bh1);
                    mma16816(s,  Qh[1], bh2, bh3);
                    mma16816(s2, Qh[0], bl0, bl1);
                    mma16816(s2, Qh[1], bl2, bl3);
                    mma16816(s2, Ql[0], bh0, bh1);
                    mma16816(s2, Ql[1], bh2, bh3);
                    const float e0 = exp2f(s[0]+s2[0]), e1 = exp2f(s[1]+s2[1]);
                    const float e2 = exp2f(s[2]+s2[2]), e3 = exp2f(s[3]+s2[3]);
                    dsum0 += e0 + e1;
                    dsum1 += e2 + e3;
                    float l0, l1, l2, l3;
                    Ph[nt2*2+0] = split2(e0, e1, &l0, &l1);
                    Ph[nt2*2+1] = split2(e2, e3, &l2, &l3);
                    Pl[nt2*2+0] = cvt2_bf16(l0, l1);
                    Pl[nt2*2+1] = cvt2_bf16(l2, l3);
                }
                const uint32_t aVbase = sVb + laneV + (uint32_t)(ch*16 + kt*8)*4u;
                #pragma unroll
                for (int ntc = 0; ntc < 4; ++ntc) {
                    uint32_t vh0, vh1, vl0, vl1;
                    ldm_x4(vh0, vh1, vl0, vl1, aVbase + (uint32_t)ntc*4224u);
                    mma16816(acc[ntc], Ph, vh0, vh1);
                    mma16816(acc[ntc], Ph, vl0, vl1);
                    mma16816(acc[ntc], Pl, vh0, vh1);
                }
            }
        }

        dsum0 += __shfl_xor_sync(0xffffffffu, dsum0, 1);
        dsum0 += __shfl_xor_sync(0xffffffffu, dsum0, 2);
        dsum1 += __shfl_xor_sync(0xffffffffu, dsum1, 1);
        dsum1 += __shfl_xor_sync(0xffffffffu, dsum1, 2);
        dsum0 = 1.f / dsum0;
        dsum1 = 1.f / dsum1;

        const int q0 = m0 + mt*16 + ld4;
        #pragma unroll
        for (int ntc = 0; ntc < 4; ++ntc) {
            const int c0 = ntc*8 + l4*2;
            const int wcol = (cbase + c0) >> 1;
            {
                float2 gv = *(const float2*)(g_gate + gbase + q0*32 + c0);
                float o0 = acc[ntc][0] * dsum0 * gv.x;
                float o1 = acc[ntc][1] * dsum0 * gv.y;
                float l0, l1;
                uint32_t hi = split2(o0, o1, &l0, &l1);
                uint32_t* base = ow + (size_t)(rbase + q0) * 128 + wcol;
                base[0]  = hi;
                base[64] = cvt2_bf16(l0, l1);
            }
            {
                float2 gv = *(const float2*)(g_gate + gbase + (q0+8)*32 + c0);
                float o0 = acc[ntc][2] * dsum1 * gv.x;
                float o1 = acc[ntc][3] * dsum1 * gv.y;
                float l0, l1;
                uint32_t hi = split2(o0, o1, &l0, &l1);
                uint32_t* base = ow + (size_t)(rbase + q0 + 8) * 128 + wcol;
                base[0]  = hi;
                base[64] = cvt2_bf16(l0, l1);
            }
        }
    }
}

// ---------------------------------------------------------------------------
// Kernel 3: out = o @ Wo.T + bo. 512 CTAs x 128 rows (occupancy fix);
// Wo split in-CTA (R14 staging); each warp one 16-row tile.
// ---------------------------------------------------------------------------
__global__ __launch_bounds__(256) void outmm_kernel(
    const float* __restrict__ Wo, const float* __restrict__ bo,
    float* __restrict__ out)
{
    __shared__ uint32_t sW[32*132];
    __shared__ float sbo[32];
    const int tid = threadIdx.x;
    {
        const int row = tid >> 3, seg = tid & 7;
        const float4* wp = (const float4*)(Wo + row*128 + seg*16);
        #pragma unroll
        for (int q4 = 0; q4 < 4; ++q4) {
            float4 w = wp[q4];
            float lx, ly, lz, lw;
            uint32_t h0 = split2(w.x, w.y, &lx, &ly);
            uint32_t h1 = split2(w.z, w.w, &lz, &lw);
            const int w0 = seg*8 + q4*2;
            sW[row*132 + w0]          = h0;
            sW[row*132 + w0 + 1]      = h1;
            sW[row*132 + 64 + w0]     = cvt2_bf16(lx, ly);
            sW[row*132 + 64 + w0 + 1] = cvt2_bf16(lz, lw);
        }
    }
    if (tid < 32) sbo[tid] = bo[tid];
    __syncthreads();

    const int warp = tid >> 5, lane = tid & 31;
    const int l4 = lane & 3, ld4 = lane >> 2;
    const int m0 = blockIdx.x * 128 + warp * 16;

    float acc[4][4];
    #pragma unroll
    for (int nt = 0; nt < 4; ++nt)
    #pragma unroll
    for (int u = 0; u < 4; ++u) acc[nt][u] = 0.f;

    const uint32_t* A = (const uint32_t*)g_ohl;

    #pragma unroll
    for (int kc = 0; kc < 4; ++kc) {
        uint32_t Ah[2][4], Al[2][4];
        #pragma unroll
        for (int kt = 0; kt < 2; ++kt) {
            const uint32_t* p0 = A + (size_t)(m0 + ld4) * 128 + kc*16 + kt*8 + l4;
            const uint32_t* p1 = p0 + 8*128;
            Ah[kt][0] = p0[0];  Ah[kt][1] = p1[0];
            Ah[kt][2] = p0[4];  Ah[kt][3] = p1[4];
            Al[kt][0] = p0[64]; Al[kt][1] = p1[64];
            Al[kt][2] = p0[68]; Al[kt][3] = p1[68];
        }
        #pragma unroll
        for (int nt = 0; nt < 4; ++nt) {
            const uint32_t* wp = sW + (nt*8 + ld4)*132 + kc*16 + l4;
            uint32_t bh[2][2], bl[2][2];
            bh[0][0]=wp[0];  bh[0][1]=wp[4];  bh[1][0]=wp[8];  bh[1][1]=wp[12];
            bl[0][0]=wp[64]; bl[0][1]=wp[68]; bl[1][0]=wp[72]; bl[1][1]=wp[76];
            #pragma unroll
            for (int kt = 0; kt < 2; ++kt) {
                mma16816(acc[nt], Ah[kt], bh[kt][0], bh[kt][1]);
                mma16816(acc[nt], Ah[kt], bl[kt][0], bl[kt][1]);
                mma16816(acc[nt], Al[kt], bh[kt][0], bh[kt][1]);
            }
        }
    }

    const int r0 = m0 + ld4;
    #pragma unroll
    for (int nt = 0; nt < 4; ++nt) {
        const int c0 = nt*8 + l4*2;
        *(float2*)(out + (size_t)r0*32 + c0) =
            make_float2(acc[nt][0] + sbo[c0], acc[nt][1] + sbo[c0+1]);
        *(float2*)(out + (size_t)(r0+8)*32 + c0) =
            make_float2(acc[nt][2] + sbo[c0], acc[nt][3] + sbo[c0+1]);
    }
}

// ---------------------------------------------------------------------------
extern "C" void kernel_launch(void* const* d_in, const int* in_sizes, int n_in,
                              void* d_out, int out_size) {
    const float* z    = (const float*)d_in[0];
    const float* ln_g = (const float*)d_in[1];
    const float* ln_b = (const float*)d_in[2];
    const float* Wq   = (const float*)d_in[3];
    const float* Wk   = (const float*)d_in[4];
    const float* Wv   = (const float*)d_in[5];
    // d_in[6] = Wb: bias is constant along the softmax axis -> cancels exactly
    const float* Wg   = (const float*)d_in[7];
    const float* bg   = (const float*)d_in[8];
    const float* Wo   = (const float*)d_in[9];
    const float* bo   = (const float*)d_in[10];
    float* out = (float*)d_out;

    cudaFuncSetAttribute(attn_kernel, cudaFuncAttributeMaxDynamicSharedMemorySize, 70656);

    ln_kernel<<<256, 256>>>(z, ln_g, ln_b);
    projmm_kernel<<<4096, 256>>>(Wq, Wk, Wv, Wg, bg);
    attn_kernel<<<1024, 256, 70656>>>();
    outmm_kernel<<<512, 256>>>(Wo, bo, out);
}